// round 1
// baseline (speedup 1.0000x reference)
#include <cuda_runtime.h>
#include <math.h>

#define BATCH 2
#define T 8
#define C 64
#define R 16
#define H 160
#define W 160
#define HW (H*W)            // 25600
#define CHW (C*HW)          // 1,638,400
#define TCHW (T*CHW)
#define C2 (2*C)            // 128
#define C4 (4*C)            // 256

// ---------------- scratch (device globals; no runtime allocation) -------------
__device__ float g_pool[BATCH*C];
__device__ float g_wd[BATCH*C*9];
__device__ float g_fp[BATCH*CHW];            // 13.1 MB
__device__ float g_fusion[(size_t)BATCH*C2*HW];      // 26.2 MB
__device__ float g_t1[(size_t)BATCH*C4*HW];          // 52.4 MB
__device__ float g_t2[(size_t)BATCH*C4*HW];          // 52.4 MB
__device__ float g_g1[BATCH*CHW];            // 13.1 MB

// ---------------- pool: mean over HW per (b,c) --------------------------------
__global__ void pool_kernel(const float* __restrict__ xbase) {
    int plane = blockIdx.x;                  // 0..BATCH*C-1
    int bi = plane >> 6, c = plane & 63;
    const float* p = xbase + (size_t)bi*TCHW + (size_t)c*HW;
    float s = 0.f;
    for (int i = threadIdx.x; i < HW; i += 256) s += p[i];
    __shared__ float red[8];
    #pragma unroll
    for (int o = 16; o; o >>= 1) s += __shfl_down_sync(0xffffffffu, s, o);
    if ((threadIdx.x & 31) == 0) red[threadIdx.x >> 5] = s;
    __syncthreads();
    if (threadIdx.x == 0) {
        float t = 0.f;
        #pragma unroll
        for (int k = 0; k < 8; k++) t += red[k];
        g_pool[plane] = t * (1.0f / (float)HW);
    }
}

// ---------------- tiny MLP: dynamic depthwise weights -------------------------
__global__ void mlp_kernel(const float* __restrict__ w1,
                           const float* __restrict__ gamma,
                           const float* __restrict__ beta,
                           const float* __restrict__ mean,
                           const float* __restrict__ var,
                           const float* __restrict__ w2,
                           const float* __restrict__ b2) {
    __shared__ float zs[BATCH*R];
    int tid = threadIdx.x;
    if (tid < BATCH*R) {
        int bi = tid / R, j = tid % R;
        float s = 0.f;
        for (int c = 0; c < C; c++) s = fmaf(g_pool[bi*C + c], w1[j*C + c], s);
        s = (s - mean[j]) * rsqrtf(var[j] + 1e-5f) * gamma[j] + beta[j];
        zs[tid] = fmaxf(s, 0.f);
    }
    __syncthreads();
    for (int o = tid; o < BATCH*C*9; o += blockDim.x) {
        int bi = o / (C*9), oo = o % (C*9);
        float s = b2[oo];
        #pragma unroll
        for (int j = 0; j < R; j++) s = fmaf(zs[bi*R + j], w2[oo*R + j], s);
        g_wd[o] = s;
    }
}

// ---------------- dynamic depthwise 3x3 on feat_prop --------------------------
__global__ void dyndw_kernel(const float* __restrict__ ybase,
                             const float* __restrict__ kc_bias) {
    int idx = blockIdx.x * 256 + threadIdx.x;        // BATCH*C*HW threads exactly
    int px = idx % HW;
    int plane = idx / HW;                            // bi*C + c
    int c = plane & 63, bi = plane >> 6;
    const float* p = ybase + (size_t)bi*TCHW + (size_t)c*HW;
    const float* wp = g_wd + plane*9;
    float w[9];
    #pragma unroll
    for (int k = 0; k < 9; k++) w[k] = wp[k];
    int y0 = px / W, x0 = px % W;
    float s = 0.f;
    #pragma unroll
    for (int kh = 0; kh < 3; kh++) {
        int yy = y0 + kh - 1;
        if ((unsigned)yy >= H) continue;
        const float* row = p + yy*W;
        #pragma unroll
        for (int kw = 0; kw < 3; kw++) {
            int xx = x0 + kw - 1;
            if ((unsigned)xx < W) s = fmaf(row[xx], w[kh*3 + kw], s);
        }
    }
    g_fp[idx] = s + kc_bias[c];
}

// ---------------- 3x3 conv, 128->128, on concat(x, fp), + leaky ---------------
// block (32,4)=128 thr; tile 32x16 output pixels; each thread: 4 rows x 8 oc.
__global__ void __launch_bounds__(128) conv3x3_kernel(const float* __restrict__ xbase,
                                                      const float* __restrict__ wgt,
                                                      const float* __restrict__ bias) {
    __shared__ float tile[18][36];
    __shared__ float ws[8][9];
    int tx = threadIdx.x, ty = threadIdx.y;
    int tid = ty*32 + tx;
    int x0 = blockIdx.x * 32;
    int y0 = blockIdx.y * 16;
    int bz = blockIdx.z;
    int bi = bz >> 4;
    int oc0 = (bz & 15) * 8;
    float acc[4][8];
    #pragma unroll
    for (int p = 0; p < 4; p++)
        #pragma unroll
        for (int o = 0; o < 8; o++) acc[p][o] = 0.f;

    const float* xp  = xbase + (size_t)bi*TCHW;
    const float* fpp = g_fp  + (size_t)bi*CHW;
    int rbase = ty * 4;

    for (int ic = 0; ic < C2; ic++) {
        const float* src = (ic < C) ? (xp + (size_t)ic*HW) : (fpp + (size_t)(ic - C)*HW);
        for (int s = tid; s < 18*34; s += 128) {
            int r = s / 34, cc = s - r*34;
            int gy = y0 + r - 1, gx = x0 + cc - 1;
            float v = 0.f;
            if ((unsigned)gy < H && (unsigned)gx < W) v = __ldg(src + gy*W + gx);
            tile[r][cc] = v;
        }
        if (tid < 72) {
            int o = tid / 9, k = tid - o*9;
            ws[o][k] = wgt[((size_t)(oc0 + o)*C2 + ic)*9 + k];
        }
        __syncthreads();
        #pragma unroll
        for (int kh = 0; kh < 3; kh++) {
            #pragma unroll
            for (int kw = 0; kw < 3; kw++) {
                float wr[8];
                #pragma unroll
                for (int o = 0; o < 8; o++) wr[o] = ws[o][kh*3 + kw];
                #pragma unroll
                for (int p = 0; p < 4; p++) {
                    float v = tile[rbase + p + kh][tx + kw];
                    #pragma unroll
                    for (int o = 0; o < 8; o++) acc[p][o] = fmaf(v, wr[o], acc[p][o]);
                }
            }
        }
        __syncthreads();
    }
    #pragma unroll
    for (int o = 0; o < 8; o++) {
        float bv = bias[oc0 + o];
        #pragma unroll
        for (int p = 0; p < 4; p++) {
            float v = acc[p][o] + bv;
            v = (v > 0.f) ? v : 0.1f * v;
            g_fusion[((size_t)bi*C2 + oc0 + o)*HW + (size_t)(y0 + rbase + p)*W + x0 + tx] = v;
        }
    }
}

// ---------------- pointwise expand 64 -> 256 (+bias) --------------------------
// block 256 thr; 64 px x 256 oc per block; thread: 8 px x 8 oc.
__global__ void __launch_bounds__(256) expand_kernel(int halfoff,
                                                     const float* __restrict__ wgt,   // [256][64]
                                                     const float* __restrict__ bias) {
    __shared__ float in_s[C][68];
    int bi  = blockIdx.y;
    int px0 = blockIdx.x * 64;
    int tid = threadIdx.x;
    const float* in = g_fusion + ((size_t)bi*C2 + halfoff)*HW + px0;
    for (int s = tid; s < C*16; s += 256) {           // float4 loads
        int ic = s >> 4, p4 = s & 15;
        float4 v = ((const float4*)(in + (size_t)ic*HW))[p4];
        *((float4*)&in_s[ic][p4*4]) = v;
    }
    __syncthreads();

    int pg = tid & 7;       // 8 groups x 8 px
    int og = tid >> 3;      // 32 groups x 8 oc
    float acc[8][8];
    #pragma unroll
    for (int p = 0; p < 8; p++)
        #pragma unroll
        for (int o = 0; o < 8; o++) acc[p][o] = 0.f;

    const float* wp = wgt + (size_t)og*8*C;
    for (int ic = 0; ic < C; ic++) {
        float4 a0 = *((const float4*)&in_s[ic][pg*8]);
        float4 a1 = *((const float4*)&in_s[ic][pg*8 + 4]);
        float a[8] = {a0.x, a0.y, a0.z, a0.w, a1.x, a1.y, a1.z, a1.w};
        float wv[8];
        #pragma unroll
        for (int o = 0; o < 8; o++) wv[o] = __ldg(wp + (size_t)o*C + ic);
        #pragma unroll
        for (int p = 0; p < 8; p++)
            #pragma unroll
            for (int o = 0; o < 8; o++) acc[p][o] = fmaf(a[p], wv[o], acc[p][o]);
    }
    float* outb = g_t1 + (size_t)bi*C4*HW + px0 + pg*8;
    #pragma unroll
    for (int o = 0; o < 8; o++) {
        int oc = og*8 + o;
        float bv = bias[oc];
        float4 v0 = make_float4(acc[0][o]+bv, acc[1][o]+bv, acc[2][o]+bv, acc[3][o]+bv);
        float4 v1 = make_float4(acc[4][o]+bv, acc[5][o]+bv, acc[6][o]+bv, acc[7][o]+bv);
        float4* op = (float4*)(outb + (size_t)oc*HW);
        op[0] = v0; op[1] = v1;
    }
}

// ---------------- static depthwise 3x3 on 256 channels (+bias) ----------------
__global__ void dwstatic_kernel(const float* __restrict__ wgt,
                                const float* __restrict__ bias) {
    int idx = blockIdx.x * 256 + threadIdx.x;        // BATCH*C4*HW threads exactly
    int px = idx % HW;
    int plane = idx / HW;                            // bi*C4 + ch
    int ch = plane & (C4 - 1);
    const float* p = g_t1 + (size_t)plane*HW;
    const float* wp = wgt + ch*9;
    float w[9];
    #pragma unroll
    for (int k = 0; k < 9; k++) w[k] = wp[k];
    int y0 = px / W, x0 = px % W;
    float s = 0.f;
    #pragma unroll
    for (int kh = 0; kh < 3; kh++) {
        int yy = y0 + kh - 1;
        if ((unsigned)yy >= H) continue;
        const float* row = p + yy*W;
        #pragma unroll
        for (int kw = 0; kw < 3; kw++) {
            int xx = x0 + kw - 1;
            if ((unsigned)xx < W) s = fmaf(row[xx], w[kh*3 + kw], s);
        }
    }
    g_t2[idx] = s + bias[ch];
}

// ---------------- pointwise contract 256 -> 64, +bias, sigmoid ----------------
// block 256 thr; 128 px x 64 oc per block; thread: 8 px x 4 oc. k chunked by 64.
// FINAL=false: writes g1 to g_g1. FINAL=true: g2 = sigmoid(.), then writes
// out = f1*g1 + f2*g2 directly to d_out slice.
template<bool FINAL>
__global__ void __launch_bounds__(256) contract_kernel(const float* __restrict__ wgt,  // [64][256]
                                                       const float* __restrict__ bias,
                                                       float* __restrict__ outbase) {
    __shared__ float in_s[64][132];
    __shared__ float w_s[64][68];
    int bi  = blockIdx.y;
    int px0 = blockIdx.x * 128;
    int tid = threadIdx.x;
    int pg = tid & 15;      // 16 groups x 8 px = 128
    int og = tid >> 4;      // 16 groups x 4 oc = 64
    float acc[8][4];
    #pragma unroll
    for (int p = 0; p < 8; p++)
        #pragma unroll
        for (int o = 0; o < 4; o++) acc[p][o] = 0.f;

    const float* in = g_t2 + (size_t)bi*C4*HW + px0;

    for (int kc = 0; kc < C4; kc += 64) {
        for (int s = tid; s < 64*32; s += 256) {     // float4 loads
            int ic = s >> 5, p4 = s & 31;
            float4 v = ((const float4*)(in + (size_t)(kc + ic)*HW))[p4];
            *((float4*)&in_s[ic][p4*4]) = v;
        }
        for (int s = tid; s < 64*64; s += 256) {     // w_s[ic][oc] = wgt[oc][kc+ic]
            int ic = s & 63, oc = s >> 6;
            w_s[ic][oc] = wgt[(size_t)oc*C4 + kc + ic];
        }
        __syncthreads();
        #pragma unroll
        for (int ic = 0; ic < 64; ic++) {
            float4 a0 = *((const float4*)&in_s[ic][pg*8]);
            float4 a1 = *((const float4*)&in_s[ic][pg*8 + 4]);
            float4 wv = *((const float4*)&w_s[ic][og*4]);
            float a[8] = {a0.x, a0.y, a0.z, a0.w, a1.x, a1.y, a1.z, a1.w};
            float wr[4] = {wv.x, wv.y, wv.z, wv.w};
            #pragma unroll
            for (int p = 0; p < 8; p++)
                #pragma unroll
                for (int o = 0; o < 4; o++) acc[p][o] = fmaf(a[p], wr[o], acc[p][o]);
        }
        __syncthreads();
    }

    #pragma unroll
    for (int o = 0; o < 4; o++) {
        int oc = og*4 + o;
        float bv = bias[oc];
        float g[8];
        #pragma unroll
        for (int p = 0; p < 8; p++) {
            float x = acc[p][o] + bv;
            g[p] = 1.0f / (1.0f + __expf(-x));
        }
        size_t poff = px0 + (size_t)pg*8;
        if (!FINAL) {
            float4* gp = (float4*)(g_g1 + ((size_t)bi*C + oc)*HW + poff);
            gp[0] = make_float4(g[0], g[1], g[2], g[3]);
            gp[1] = make_float4(g[4], g[5], g[6], g[7]);
        } else {
            const float4* f1p = (const float4*)(g_fusion + ((size_t)bi*C2 + oc)*HW + poff);
            const float4* f2p = (const float4*)(g_fusion + ((size_t)bi*C2 + C + oc)*HW + poff);
            const float4* g1p = (const float4*)(g_g1 + ((size_t)bi*C + oc)*HW + poff);
            float4* op = (float4*)(outbase + (size_t)bi*TCHW + (size_t)oc*HW + poff);
            #pragma unroll
            for (int q = 0; q < 2; q++) {
                float4 f1 = f1p[q], f2 = f2p[q], g1 = g1p[q];
                float4 r;
                r.x = f1.x*g1.x + f2.x*g[q*4+0];
                r.y = f1.y*g1.y + f2.y*g[q*4+1];
                r.z = f1.z*g1.z + f2.z*g[q*4+2];
                r.w = f1.w*g1.w + f2.w*g[q*4+3];
                op[q] = r;
            }
        }
    }
}

// ---------------- launcher -----------------------------------------------------
extern "C" void kernel_launch(void* const* d_in, const int* in_sizes, int n_in,
                              void* d_out, int out_size) {
    (void)in_sizes; (void)n_in; (void)out_size;
    const float* feature   = (const float*)d_in[0];
    const float* kc_w1     = (const float*)d_in[1];
    const float* kc_gamma  = (const float*)d_in[2];
    const float* kc_beta   = (const float*)d_in[3];
    const float* kc_mean   = (const float*)d_in[4];
    const float* kc_var    = (const float*)d_in[5];
    const float* kc_w2     = (const float*)d_in[6];
    const float* kc_b2     = (const float*)d_in[7];
    const float* kc_bias   = (const float*)d_in[8];
    const float* conv1_w   = (const float*)d_in[9];
    const float* conv1_b   = (const float*)d_in[10];
    const float* pi1_w     = (const float*)d_in[11];
    const float* pi1_b     = (const float*)d_in[12];
    const float* dw1_w     = (const float*)d_in[13];
    const float* dw1_b     = (const float*)d_in[14];
    const float* po1_w     = (const float*)d_in[15];
    const float* po1_b     = (const float*)d_in[16];
    const float* pi2_w     = (const float*)d_in[17];
    const float* pi2_b     = (const float*)d_in[18];
    const float* dw2_w     = (const float*)d_in[19];
    const float* dw2_b     = (const float*)d_in[20];
    const float* po2_w     = (const float*)d_in[21];
    const float* po2_b     = (const float*)d_in[22];
    float* out = (float*)d_out;

    // out[:, T-1] = feature[:, T-1]
    for (int bi = 0; bi < BATCH; bi++) {
        size_t off = ((size_t)bi*T + (T-1)) * CHW;
        cudaMemcpyAsync(out + off, feature + off, (size_t)CHW*sizeof(float),
                        cudaMemcpyDeviceToDevice, 0);
    }

    for (int i = T - 2; i >= 0; --i) {
        const float* xbase = feature + (size_t)i*CHW;         // x_feat slice (b-stride TCHW)
        const float* ybase = out + (size_t)(i+1)*CHW;         // feat_prop slice

        pool_kernel<<<BATCH*C, 256>>>(xbase);
        mlp_kernel<<<1, 128>>>(kc_w1, kc_gamma, kc_beta, kc_mean, kc_var, kc_w2, kc_b2);
        dyndw_kernel<<<(BATCH*CHW)/256, 256>>>(ybase, kc_bias);
        conv3x3_kernel<<<dim3(W/32, H/16, BATCH*16), dim3(32, 4)>>>(xbase, conv1_w, conv1_b);

        // gate 1 -> g_g1
        expand_kernel<<<dim3(HW/64, BATCH), 256>>>(0, pi1_w, pi1_b);
        dwstatic_kernel<<<(BATCH*C4*HW)/256, 256>>>(dw1_w, dw1_b);
        contract_kernel<false><<<dim3(HW/128, BATCH), 256>>>(po1_w, po1_b, nullptr);

        // gate 2 -> fused final combine, writes out[:, i]
        expand_kernel<<<dim3(HW/64, BATCH), 256>>>(C, pi2_w, pi2_b);
        dwstatic_kernel<<<(BATCH*C4*HW)/256, 256>>>(dw2_w, dw2_b);
        contract_kernel<true><<<dim3(HW/128, BATCH), 256>>>(po2_w, po2_b, out + (size_t)i*CHW);
    }
}